// round 3
// baseline (speedup 1.0000x reference)
#include <cuda_runtime.h>

// Shapes (fixed by the problem)
#define BATCH   2
#define SEQ     4096
#define HEADS   16
#define DHEAD   64      // p
#define DSTATE  128     // n
#define LBLK    64      // block_len l

// Derivation: reference's decay_chunk row z=C (upper-triangular mask j>=i)
// keeps ONLY column j=C -> output depends on the LAST chunk alone:
//   out[b,h,p,n] = sum_l exp(2*S - cs[l]) * X[b,T-64+l,h,p] * B[b,T-64+l,h,n]
// with cs = inclusive cumsum of A over the last 64 steps, S = cs[63].

__global__ __launch_bounds__(256)
void chunk_state_last_kernel(const float* __restrict__ X,
                             const float* __restrict__ A,
                             const float* __restrict__ B,
                             float* __restrict__ out)
{
    const int bh = blockIdx.x;          // 0..31
    const int b  = bh >> 4;
    const int h  = bh & 15;
    const int n0 = blockIdx.y * 32;     // n-tile origin (4 tiles of 32)
    const int tid = threadIdx.x;        // 256 threads
    const int t0 = SEQ - LBLK;

    // float4-accessed smem MUST be 16B aligned (STS.128/LDS.128 trap otherwise)
    __shared__ __align__(16) float  Xs[LBLK][DHEAD];  // 16 KB [l][p]
    __shared__ __align__(16) float4 Bs[LBLK][8];      //  8 KB [l][n/4]
    __shared__ float w[LBLK];
    __shared__ float warp_sum[2];

    // ---- A slice + inclusive scan (warp shuffles, 2 warps) ----
    float cs_v = 0.f;
    if (tid < LBLK) {
        const int lane = tid & 31;
        float v = A[((size_t)b * SEQ + t0 + tid) * HEADS + h];
        #pragma unroll
        for (int off = 1; off < 32; off <<= 1) {
            float up = __shfl_up_sync(0xFFFFFFFFu, v, off);
            if (lane >= off) v += up;
        }
        if (lane == 31) warp_sum[tid >> 5] = v;
        cs_v = v;
    }
    __syncthreads();                    // uniform barrier: warp_sum visible
    if (tid < LBLK) {
        float cs = cs_v + ((tid >> 5) == 1 ? warp_sum[0] : 0.f);
        float S  = warp_sum[0] + warp_sum[1];   // total = cs[63]
        w[tid] = expf(2.f * S - cs);
    }

    // ---- stage X tile: 64 rows x 64 floats (1024 float4) ----
    const float* Xbase = X + (((size_t)b * SEQ + t0) * HEADS + h) * DHEAD;
    for (int i = tid; i < LBLK * 16; i += 256) {
        int l = i >> 4, c = i & 15;
        ((float4*)Xs[l])[c] =
            ((const float4*)(Xbase + (size_t)l * HEADS * DHEAD))[c];
    }
    // ---- stage B tile: 64 rows x 32 floats (512 float4) ----
    const float* Bbase = B + (((size_t)b * SEQ + t0) * HEADS + h) * DSTATE + n0;
    for (int i = tid; i < LBLK * 8; i += 256) {
        int l = i >> 3, c = i & 7;
        Bs[l][c] = ((const float4*)(Bbase + (size_t)l * HEADS * DSTATE))[c];
    }
    __syncthreads();

    // ---- rank-64 weighted outer-product; 2p x 4n per thread ----
    const int tn = tid & 7;    // n = n0 + tn*4 + j
    const int tp = tid >> 3;   // p = tp*2 + {0,1}
    float acc0x = 0.f, acc0y = 0.f, acc0z = 0.f, acc0w = 0.f;
    float acc1x = 0.f, acc1y = 0.f, acc1z = 0.f, acc1w = 0.f;

    #pragma unroll 8
    for (int l = 0; l < LBLK; l++) {
        const float wl = w[l];
        const float x0 = Xs[l][tp * 2]     * wl;
        const float x1 = Xs[l][tp * 2 + 1] * wl;
        const float4 bv = Bs[l][tn];
        acc0x += x0 * bv.x; acc0y += x0 * bv.y; acc0z += x0 * bv.z; acc0w += x0 * bv.w;
        acc1x += x1 * bv.x; acc1y += x1 * bv.y; acc1z += x1 * bv.z; acc1w += x1 * bv.w;
    }

    float* obase = out + ((size_t)(b * HEADS + h)) * DHEAD * DSTATE;
    {
        int p = tp * 2;
        *(float4*)(obase + (size_t)p * DSTATE + n0 + tn * 4) =
            make_float4(acc0x, acc0y, acc0z, acc0w);
        p = tp * 2 + 1;
        *(float4*)(obase + (size_t)p * DSTATE + n0 + tn * 4) =
            make_float4(acc1x, acc1y, acc1z, acc1w);
    }
}

extern "C" void kernel_launch(void* const* d_in, const int* in_sizes, int n_in,
                              void* d_out, int out_size)
{
    const float* X = (const float*)d_in[0];   // (2,4096,16,64)  f32
    const float* A = (const float*)d_in[1];   // (2,4096,16)     f32
    const float* B = (const float*)d_in[2];   // (2,4096,16,128) f32
    float* out = (float*)d_out;               // (2,16,64,128)   f32

    dim3 grid(BATCH * HEADS, DSTATE / 32);    // 32 x 4 = 128 CTAs
    chunk_state_last_kernel<<<grid, 256>>>(X, A, B, out);
}

// round 5
// speedup vs baseline: 1.2545x; 1.2545x over previous
#include <cuda_runtime.h>
#include <cstdint>

// Shapes (fixed by the problem)
#define BATCH   2
#define SEQ     4096
#define HEADS   16
#define DHEAD   64      // p
#define DSTATE  128     // n
#define LBLK    64      // block_len l

// Derivation: reference's decay_chunk row z=C (upper-triangular mask j>=i)
// keeps ONLY column j=C -> output depends on the LAST chunk alone:
//   out[b,h,p,n] = sum_l exp(2*S - cs[l]) * X[b,T-64+l,h,p] * B[b,T-64+l,h,n]
// with cs = inclusive cumsum of A over the last 64 steps, S = cs[63].

__device__ __forceinline__ void cp_async16(uint32_t saddr, const void* gptr) {
    asm volatile("cp.async.cg.shared.global [%0], [%1], 16;"
                 :: "r"(saddr), "l"(gptr));
}

__global__ __launch_bounds__(256)
void chunk_state_last_kernel(const float* __restrict__ X,
                             const float* __restrict__ A,
                             const float* __restrict__ B,
                             float* __restrict__ out)
{
    const int bh = blockIdx.x;          // 0..31
    const int b  = bh >> 4;
    const int h  = bh & 15;
    const int n0 = blockIdx.y * 32;     // n-tile origin (4 tiles of 32)
    const int tid = threadIdx.x;        // 256 threads
    const int t0 = SEQ - LBLK;

    __shared__ __align__(16) float  Xs[LBLK][DHEAD];  // 16 KB [l][p]
    __shared__ __align__(16) float4 Bs[LBLK][8];      //  8 KB [l][n/4]
    __shared__ __align__(16) float  w[LBLK];

    // ---- 1) async-stage X and B tiles (independent of A; overlaps A scan) ----
    const float* Xbase = X + (((size_t)b * SEQ + t0) * HEADS + h) * DHEAD;
    const uint32_t xs_s = (uint32_t)__cvta_generic_to_shared(&Xs[0][0]);
    #pragma unroll
    for (int k = 0; k < 4; k++) {
        int i = tid + k * 256;          // 0..1023 float4 slots
        int l = i >> 4, c = i & 15;
        cp_async16(xs_s + i * 16, Xbase + (size_t)l * HEADS * DHEAD + c * 4);
    }
    const float* Bbase = B + (((size_t)b * SEQ + t0) * HEADS + h) * DSTATE + n0;
    const uint32_t bs_s = (uint32_t)__cvta_generic_to_shared(&Bs[0][0]);
    #pragma unroll
    for (int k = 0; k < 2; k++) {
        int i = tid + k * 256;          // 0..511 float4 slots
        int l = i >> 3, c = i & 7;
        cp_async16(bs_s + i * 16, Bbase + (size_t)l * HEADS * DSTATE + c * 4);
    }
    asm volatile("cp.async.commit_group;");

    // ---- 2) warp 0 only: A scan (2 values/lane, pair-scan) + weights ----
    if (tid < 32) {
        const int lane = tid;
        const float* Abase = A + ((size_t)b * SEQ + t0) * HEADS + h;
        float a0 = Abase[(size_t)(2 * lane)     * HEADS];
        float a1 = Abase[(size_t)(2 * lane + 1) * HEADS];
        float v = a0 + a1;              // pair sum
        #pragma unroll
        for (int off = 1; off < 32; off <<= 1) {
            float up = __shfl_up_sync(0xFFFFFFFFu, v, off);
            if (lane >= off) v += up;
        }
        float S   = __shfl_sync(0xFFFFFFFFu, v, 31);  // total sum cs[63]
        float cs1 = v;                  // inclusive cumsum through 2*lane+1
        float cs0 = v - a1;             // inclusive cumsum through 2*lane
        w[2 * lane]     = __expf(2.f * S - cs0);
        w[2 * lane + 1] = __expf(2.f * S - cs1);
    }

    asm volatile("cp.async.wait_group 0;");
    __syncthreads();                    // single barrier: tiles + w ready

    // ---- 3) premultiply w into Xs rows (in place) ----
    #pragma unroll
    for (int k = 0; k < 4; k++) {
        int i = tid + k * 256;          // float4 slot
        int l = i >> 4;
        float4* p4 = (float4*)&Xs[0][0] + i;
        float4 v = *p4;
        float wl = w[l];
        v.x *= wl; v.y *= wl; v.z *= wl; v.w *= wl;
        *p4 = v;
    }
    __syncthreads();

    // ---- 4) rank-64 outer product; 2p x 4n per thread ----
    const int tn = tid & 7;             // n = n0 + tn*4 + j
    const int tp = tid >> 3;            // p = tp*2 + {0,1}
    float acc0x = 0.f, acc0y = 0.f, acc0z = 0.f, acc0w = 0.f;
    float acc1x = 0.f, acc1y = 0.f, acc1z = 0.f, acc1w = 0.f;

    #pragma unroll 8
    for (int l = 0; l < LBLK; l++) {
        const float2 xv = *(const float2*)&Xs[l][tp * 2];  // w pre-applied
        const float4 bv = Bs[l][tn];
        acc0x += xv.x * bv.x; acc0y += xv.x * bv.y;
        acc0z += xv.x * bv.z; acc0w += xv.x * bv.w;
        acc1x += xv.y * bv.x; acc1y += xv.y * bv.y;
        acc1z += xv.y * bv.z; acc1w += xv.y * bv.w;
    }

    float* obase = out + ((size_t)(b * HEADS + h)) * DHEAD * DSTATE;
    {
        int p = tp * 2;
        *(float4*)(obase + (size_t)p * DSTATE + n0 + tn * 4) =
            make_float4(acc0x, acc0y, acc0z, acc0w);
        p = tp * 2 + 1;
        *(float4*)(obase + (size_t)p * DSTATE + n0 + tn * 4) =
            make_float4(acc1x, acc1y, acc1z, acc1w);
    }
}

extern "C" void kernel_launch(void* const* d_in, const int* in_sizes, int n_in,
                              void* d_out, int out_size)
{
    const float* X = (const float*)d_in[0];   // (2,4096,16,64)  f32
    const float* A = (const float*)d_in[1];   // (2,4096,16)     f32
    const float* B = (const float*)d_in[2];   // (2,4096,16,128) f32
    float* out = (float*)d_out;               // (2,16,64,128)   f32

    dim3 grid(BATCH * HEADS, DSTATE / 32);    // 32 x 4 = 128 CTAs
    chunk_state_last_kernel<<<grid, 256>>>(X, A, B, out);
}